// round 3
// baseline (speedup 1.0000x reference)
#include <cuda_runtime.h>
#include <cstdint>

// ---------------------------------------------------------------------------
// Edge-MLP link predictor, factorized:
//   P[n][0:128]   = h[n] @ W1[0:128,:]   + b1      (Pa, bias folded)
//   P[n][128:256] = h[n] @ W1[128:256,:]           (Pb)
//   out[e] = sigmoid( relu(Pa[src_e] + Pb[dst_e]) . W2 + b2 )
// Phase 1: fp32 SGEMM [M x 128] @ [128 x 256] using packed fma.rn.f32x2.
// Phase 2: warp-per-edge L2-resident gather + fused epilogue.
// edge_index arrives as int32 (JAX canonicalizes int64 -> int32).
// ---------------------------------------------------------------------------

static constexpr int HID = 128;
static constexpr int MAXN = 50000;

__device__ float g_P[(size_t)MAXN * 256];

// ---------------- Phase 1: node projection SGEMM ----------------
// Grid: (ceil(M/128), 2). CTA tile: 128 rows x 128 cols, K=128 (full).
// SMEM: As = A^T swizzled [k][m] (128x128 fp32), Bs = [k][n] (128x128 fp32).
// Thread (ty=tid/16, tx=tid%16) computes rows ty*8..+7, cols tx*8..+7.
// A swizzle: float word addr(k,m) = k*128 + ((u ^ ((k>>2)&7))<<2) + (m&3),
//   u = m>>2.  STS during transpose is conflict-free; LDS per-k is broadcast.

__global__ void __launch_bounds__(256, 1)
node_proj_kernel(const float* __restrict__ hfeat,
                 const float* __restrict__ W1,   // [256,128] row-major
                 const float* __restrict__ b1,   // [128]
                 int M) {
    extern __shared__ float smem[];
    float* As = smem;              // 128*128
    float* Bs = smem + 128 * 128;  // 128*128

    const int tid = threadIdx.x;
    const int m0 = blockIdx.x * 128;
    const int nt = blockIdx.y;     // 0 -> Pa (W1 rows 0..127), 1 -> Pb (rows 128..255)

    // ---- load B tile: Bs[k][n] = W1[nt*128 + k][n] ----
    {
        const float4* Wg = reinterpret_cast<const float4*>(W1) + (size_t)nt * 128 * 32;
        float4* Bs4 = reinterpret_cast<float4*>(Bs);
        #pragma unroll
        for (int i = 0; i < 16; i++) {
            int id = tid + i * 256;
            Bs4[id] = Wg[id];   // same [k][n4] layout, direct copy
        }
    }

    // ---- load + transpose A: As(k, m) = h[m0+m][k], swizzled ----
    {
        const int lane = tid & 31, w = tid >> 5;
        const int kq = lane & 7, mloc = lane >> 3;
        #pragma unroll
        for (int ir = 0; ir < 4; ir++) {
            int m = ir * 32 + w * 4 + mloc;
            int gm = m0 + m;
            if (gm < M) {
                int u = m >> 2, lo = m & 3;
                #pragma unroll
                for (int ik = 0; ik < 4; ik++) {
                    int kq4 = ik * 8 + kq;               // float4 col index
                    float4 v = reinterpret_cast<const float4*>(hfeat)[(size_t)gm * 32 + kq4];
                    int kb = kq4 * 4;
                    #pragma unroll
                    for (int j = 0; j < 4; j++) {
                        int k = kb + j;                  // (k>>2)&7 == kq4&7 == kq
                        int word = k * 128 + (((u ^ (kq4 & 7)) << 2) | lo);
                        As[word] = (&v.x)[j];
                    }
                }
            }
        }
    }
    __syncthreads();

    // ---- main loop: 8x8 register tile, packed f32x2 FMA ----
    const int ty = tid >> 4, tx = tid & 15;
    unsigned long long acc[8][4];
    #pragma unroll
    for (int m = 0; m < 8; m++)
        #pragma unroll
        for (int np = 0; np < 4; np++) acc[m][np] = 0ull;

    const float4* As4 = reinterpret_cast<const float4*>(As);

    #pragma unroll 8
    for (int k = 0; k < 128; k++) {
        const int s = (k >> 2) & 7;
        float4 a0 = As4[k * 32 + ((2 * ty) ^ s)];
        float4 a1 = As4[k * 32 + ((2 * ty + 1) ^ s)];
        const ulonglong2* B2 = reinterpret_cast<const ulonglong2*>(Bs + k * 128 + tx * 8);
        ulonglong2 b01 = B2[0];
        ulonglong2 b23 = B2[1];
        unsigned long long bq[4] = {b01.x, b01.y, b23.x, b23.y};
        float am[8] = {a0.x, a0.y, a0.z, a0.w, a1.x, a1.y, a1.z, a1.w};
        #pragma unroll
        for (int m = 0; m < 8; m++) {
            unsigned long long a2;
            asm("mov.b64 %0, {%1, %1};" : "=l"(a2) : "f"(am[m]));
            #pragma unroll
            for (int np = 0; np < 4; np++)
                asm("fma.rn.f32x2 %0, %1, %2, %0;"
                    : "+l"(acc[m][np]) : "l"(a2), "l"(bq[np]));
        }
    }

    // ---- epilogue: fold b1 into Pa half, store to g_P ----
    float bias[8];
    if (nt == 0) {
        float4 bv0 = reinterpret_cast<const float4*>(b1)[tx * 2];
        float4 bv1 = reinterpret_cast<const float4*>(b1)[tx * 2 + 1];
        bias[0] = bv0.x; bias[1] = bv0.y; bias[2] = bv0.z; bias[3] = bv0.w;
        bias[4] = bv1.x; bias[5] = bv1.y; bias[6] = bv1.z; bias[7] = bv1.w;
    } else {
        #pragma unroll
        for (int j = 0; j < 8; j++) bias[j] = 0.0f;
    }

    #pragma unroll
    for (int m = 0; m < 8; m++) {
        int gm = m0 + ty * 8 + m;
        if (gm < M) {
            float o[8];
            #pragma unroll
            for (int np = 0; np < 4; np++) {
                float lo, hi;
                asm("mov.b64 {%0, %1}, %2;" : "=f"(lo), "=f"(hi) : "l"(acc[m][np]));
                o[2 * np]     = lo + bias[2 * np];
                o[2 * np + 1] = hi + bias[2 * np + 1];
            }
            float* dst = g_P + (size_t)gm * 256 + nt * 128 + tx * 8;
            reinterpret_cast<float4*>(dst)[0] = make_float4(o[0], o[1], o[2], o[3]);
            reinterpret_cast<float4*>(dst)[1] = make_float4(o[4], o[5], o[6], o[7]);
        }
    }
}

// ---------------- Phase 2: warp-per-edge gather + epilogue ----------------

__global__ void __launch_bounds__(256)
edge_kernel(const int* __restrict__ eidx,       // [2, E] int32
            const float* __restrict__ W2,        // [128]
            const float* __restrict__ b2,        // [1]
            float* __restrict__ out, int E) {
    const int warp = (blockIdx.x * blockDim.x + threadIdx.x) >> 5;
    const int lane = threadIdx.x & 31;
    if (warp >= E) return;

    const int src = __ldg(eidx + warp);
    const int dst = __ldg(eidx + E + warp);

    float4 va = reinterpret_cast<const float4*>(g_P + (size_t)src * 256)[lane];
    float4 vb = reinterpret_cast<const float4*>(g_P + (size_t)dst * 256 + 128)[lane];
    float4 w  = reinterpret_cast<const float4*>(W2)[lane];

    float acc = fmaxf(va.x + vb.x, 0.0f) * w.x;
    acc = fmaf(fmaxf(va.y + vb.y, 0.0f), w.y, acc);
    acc = fmaf(fmaxf(va.z + vb.z, 0.0f), w.z, acc);
    acc = fmaf(fmaxf(va.w + vb.w, 0.0f), w.w, acc);

    #pragma unroll
    for (int off = 16; off > 0; off >>= 1)
        acc += __shfl_xor_sync(0xFFFFFFFFu, acc, off);

    if (lane == 0) {
        float x = acc + __ldg(b2);
        out[warp] = 1.0f / (1.0f + expf(-x));
    }
}

// ---------------- launch ----------------

extern "C" void kernel_launch(void* const* d_in, const int* in_sizes, int n_in,
                              void* d_out, int out_size) {
    const float* hfeat = (const float*)d_in[0];
    const int*   eidx  = (const int*)d_in[1];
    const float* W1    = (const float*)d_in[2];
    const float* b1    = (const float*)d_in[3];
    const float* W2    = (const float*)d_in[4];
    const float* b2    = (const float*)d_in[5];
    float* out = (float*)d_out;

    const int M = in_sizes[0] / HID;     // number of nodes
    const int E = in_sizes[1] / 2;       // number of edges

    cudaFuncSetAttribute(node_proj_kernel,
                         cudaFuncAttributeMaxDynamicSharedMemorySize,
                         2 * 128 * 128 * (int)sizeof(float));

    dim3 g1((M + 127) / 128, 2);
    node_proj_kernel<<<g1, 256, 2 * 128 * 128 * sizeof(float)>>>(hfeat, W1, b1, M);

    const int blocks2 = (E + 7) / 8;     // 8 edges (warps) per 256-thread CTA
    edge_kernel<<<blocks2, 256>>>(eidx, W2, b2, out, E);
}

// round 5
// speedup vs baseline: 2.8450x; 2.8450x over previous
#include <cuda_runtime.h>
#include <cuda_fp16.h>
#include <cstdint>

// ---------------------------------------------------------------------------
// Edge-MLP link predictor, factorized + tensor-core phase 1:
//   P[n][0:128]   = h[n] @ W1[0:128,:]   + b1   (Pa, bias folded, fp16 store)
//   P[n][128:256] = h[n] @ W1[128:256,:]        (Pb, fp16 store)
//   out[e] = sigmoid( relu(Pa[src_e] + Pb[dst_e]) . W2 + b2 )
// Phase 1: mma.sync.m16n8k16 (fp16 in, fp32 accum) — baseline PTX, no tcgen05.
// Phase 2: half-warp per edge, 8 edges/warp, batched gathers for high MLP.
// ---------------------------------------------------------------------------

static constexpr int HID = 128;
static constexpr int MAXN = 50000;

__device__ __half g_P[(size_t)MAXN * 256];   // [node][0:128]=Pa, [128:256]=Pb

// ---------------- helpers ----------------

__device__ __forceinline__ uint32_t smem_u32(const void* p) {
    uint32_t a;
    asm("{ .reg .u64 t; cvta.to.shared.u64 t, %1; cvt.u32.u64 %0, t; }"
        : "=r"(a) : "l"(p));
    return a;
}

__device__ __forceinline__ uint32_t h2_bits(__half2 h) {
    return *reinterpret_cast<uint32_t*>(&h);
}

__device__ __forceinline__ void ldm_x4(uint32_t& a0, uint32_t& a1, uint32_t& a2,
                                       uint32_t& a3, uint32_t addr) {
    asm volatile("ldmatrix.sync.aligned.m8n8.x4.shared.b16 {%0,%1,%2,%3}, [%4];"
                 : "=r"(a0), "=r"(a1), "=r"(a2), "=r"(a3) : "r"(addr));
}

__device__ __forceinline__ void ldm_x2_t(uint32_t& b0, uint32_t& b1, uint32_t addr) {
    asm volatile("ldmatrix.sync.aligned.m8n8.x2.trans.shared.b16 {%0,%1}, [%2];"
                 : "=r"(b0), "=r"(b1) : "r"(addr));
}

__device__ __forceinline__ void mma16816(float& d0, float& d1, float& d2, float& d3,
                                         uint32_t a0, uint32_t a1, uint32_t a2,
                                         uint32_t a3, uint32_t b0, uint32_t b1) {
    asm volatile(
        "mma.sync.aligned.m16n8k16.row.col.f32.f16.f16.f32 "
        "{%0,%1,%2,%3}, {%4,%5,%6,%7}, {%8,%9}, {%0,%1,%2,%3};"
        : "+f"(d0), "+f"(d1), "+f"(d2), "+f"(d3)
        : "r"(a0), "r"(a1), "r"(a2), "r"(a3), "r"(b0), "r"(b1));
}

// ---------------- Phase 1: node projection GEMM (tensor cores) ----------------
// Grid (ceil(M/128), 2). CTA tile: 128 m x 128 n, K=128 full.
// SMEM rows padded to 136 halfs (272B) -> ldmatrix conflict-free.
// 8 warps, warp tile 64m x 32n -> 4x4 grid of m16n8k16, accum 64 fp32/thread.

static constexpr int SROW = 136;                 // halfs per padded smem row
static constexpr uint32_t SROWB = SROW * 2;      // 272 bytes
static constexpr uint32_t P1_SMEM = 2u * 128u * SROWB;  // 69632 B

__global__ void __launch_bounds__(256, 1)
node_proj_kernel(const float* __restrict__ hfeat,
                 const float* __restrict__ W1,   // [256,128] row-major
                 const float* __restrict__ b1,   // [128]
                 int M) {
    extern __shared__ __align__(16) char smem[];
    char* As = smem;                         // [128][SROW] halfs, row = m
    char* Bs = smem + 128 * SROWB;           // [128][SROW] halfs, row = k
    const uint32_t as_b = smem_u32(As);
    const uint32_t bs_b = smem_u32(Bs);

    const int tid  = threadIdx.x;
    const int m0   = blockIdx.x * 128;
    const int half = blockIdx.y;             // 0 -> Pa (W1 rows 0..127), 1 -> Pb

    // ---- load A: h[m0+m][0:128] fp32 -> fp16, and B: W1[half*128+k][0:128] ----
    #pragma unroll
    for (int it = 0; it < 16; it++) {
        int i  = tid + it * 256;             // 4096 float4 groups
        int r  = i >> 5;                     // row (m or k)
        int c4 = i & 31;                     // float4 index within row
        int gm = m0 + r; if (gm >= M) gm = M - 1;
        float4 va = reinterpret_cast<const float4*>(hfeat)[(size_t)gm * 32 + c4];
        *reinterpret_cast<uint2*>(As + r * SROWB + c4 * 8) =
            make_uint2(h2_bits(__floats2half2_rn(va.x, va.y)),
                       h2_bits(__floats2half2_rn(va.z, va.w)));
        float4 vb = reinterpret_cast<const float4*>(W1)[(size_t)(half * 128 + r) * 32 + c4];
        *reinterpret_cast<uint2*>(Bs + r * SROWB + c4 * 8) =
            make_uint2(h2_bits(__floats2half2_rn(vb.x, vb.y)),
                       h2_bits(__floats2half2_rn(vb.z, vb.w)));
    }
    __syncthreads();

    const int wid  = tid >> 5;
    const int lane = tid & 31;
    const int wm = (wid >> 2) * 64;          // warp m-origin (0 or 64)
    const int wn = (wid & 3) * 32;           // warp n-origin (0,32,64,96)

    float d[4][4][4];
    #pragma unroll
    for (int fm = 0; fm < 4; fm++)
        #pragma unroll
        for (int fn = 0; fn < 4; fn++)
            #pragma unroll
            for (int r = 0; r < 4; r++) d[fm][fn][r] = 0.0f;

    const int l15 = lane & 15;
    const int khalf = (lane >> 4) * 8;

    #pragma unroll
    for (int kk = 0; kk < 8; kk++) {
        const int k16 = kk * 16;
        uint32_t a[4][4];
        #pragma unroll
        for (int fm = 0; fm < 4; fm++) {
            uint32_t addr = as_b + (uint32_t)(wm + fm * 16 + l15) * SROWB +
                            (uint32_t)(k16 + khalf) * 2;
            ldm_x4(a[fm][0], a[fm][1], a[fm][2], a[fm][3], addr);
        }
        uint32_t b[4][2];
        #pragma unroll
        for (int fn = 0; fn < 4; fn++) {
            uint32_t addr = bs_b + (uint32_t)(k16 + l15) * SROWB +
                            (uint32_t)(wn + fn * 8) * 2;
            ldm_x2_t(b[fn][0], b[fn][1], addr);
        }
        #pragma unroll
        for (int fm = 0; fm < 4; fm++)
            #pragma unroll
            for (int fn = 0; fn < 4; fn++)
                mma16816(d[fm][fn][0], d[fm][fn][1], d[fm][fn][2], d[fm][fn][3],
                         a[fm][0], a[fm][1], a[fm][2], a[fm][3],
                         b[fn][0], b[fn][1]);
    }

    // ---- epilogue: +b1 (half==0), fp16 pack, store to g_P ----
    const int r0 = lane >> 2;                // 0..7
    const int c0 = (lane & 3) * 2;           // 0,2,4,6
    #pragma unroll
    for (int fn = 0; fn < 4; fn++) {
        const int n = wn + fn * 8 + c0;      // even, 0..126
        float2 bias = make_float2(0.0f, 0.0f);
        if (half == 0) bias = *reinterpret_cast<const float2*>(b1 + n);
        #pragma unroll
        for (int fm = 0; fm < 4; fm++) {
            #pragma unroll
            for (int sub = 0; sub < 2; sub++) {
                int gm = m0 + wm + fm * 16 + r0 + sub * 8;
                if (gm < M) {
                    float x = d[fm][fn][sub * 2]     + bias.x;
                    float y = d[fm][fn][sub * 2 + 1] + bias.y;
                    __half2 hv = __floats2half2_rn(x, y);
                    *reinterpret_cast<__half2*>(g_P + (size_t)gm * 256 + half * 128 + n) = hv;
                }
            }
        }
    }
}

// ---------------- Phase 2: 8 edges per warp, half-warp per edge ----------------

__global__ void __launch_bounds__(256)
edge_kernel(const int* __restrict__ eidx,    // [2, E] int32
            const float* __restrict__ W2,    // [128]
            const float* __restrict__ b2,    // [1]
            float* __restrict__ out, int E) {
    const int warp = (blockIdx.x * blockDim.x + threadIdx.x) >> 5;
    const int lane = threadIdx.x & 31;
    const int hl  = lane >> 4;               // half-warp id (0/1)
    const int l16 = lane & 15;
    const int e0  = warp * 8;                // 8 edges per warp
    if (e0 >= E) return;

    // W2 slice for this lane: 8 floats (L1-resident)
    float4 w0 = reinterpret_cast<const float4*>(W2)[l16 * 2];
    float4 w1 = reinterpret_cast<const float4*>(W2)[l16 * 2 + 1];

    // batch-load indices (4 iterations x 2 edges-per-warp via half-warps)
    int ev[4], sv[4], dv[4];
    #pragma unroll
    for (int i = 0; i < 4; i++) {
        ev[i] = e0 + i * 2 + hl;
        bool ok = ev[i] < E;
        sv[i] = ok ? __ldg(eidx + ev[i]) : 0;
        dv[i] = ok ? __ldg(eidx + E + ev[i]) : 0;
    }
    // batch-issue all 8 gathers (16B per lane each) for MLP
    uint4 va[4], vb[4];
    #pragma unroll
    for (int i = 0; i < 4; i++) {
        va[i] = *reinterpret_cast<const uint4*>(g_P + (size_t)sv[i] * 256 + l16 * 8);
        vb[i] = *reinterpret_cast<const uint4*>(g_P + (size_t)dv[i] * 256 + 128 + l16 * 8);
    }

    const float b2v = __ldg(b2);
    #pragma unroll
    for (int i = 0; i < 4; i++) {
        const uint32_t* pa = &va[i].x;
        const uint32_t* pb = &vb[i].x;
        float acc = 0.0f;
        #pragma unroll
        for (int q = 0; q < 4; q++) {
            float2 fa = __half22float2(*reinterpret_cast<const __half2*>(&pa[q]));
            float2 fb = __half22float2(*reinterpret_cast<const __half2*>(&pb[q]));
            float wx = (q < 2) ? ((q == 0) ? w0.x : w0.z) : ((q == 2) ? w1.x : w1.z);
            float wy = (q < 2) ? ((q == 0) ? w0.y : w0.w) : ((q == 2) ? w1.y : w1.w);
            acc = fmaf(fmaxf(fa.x + fb.x, 0.0f), wx, acc);
            acc = fmaf(fmaxf(fa.y + fb.y, 0.0f), wy, acc);
        }
        #pragma unroll
        for (int off = 8; off > 0; off >>= 1)
            acc += __shfl_xor_sync(0xFFFFFFFFu, acc, off);
        if (l16 == 0 && ev[i] < E) {
            float x = acc + b2v;
            out[ev[i]] = 1.0f / (1.0f + expf(-x));
        }
    }
}

// ---------------- launch ----------------

extern "C" void kernel_launch(void* const* d_in, const int* in_sizes, int n_in,
                              void* d_out, int out_size) {
    const float* hfeat = (const float*)d_in[0];
    const int*   eidx  = (const int*)d_in[1];
    const float* W1    = (const float*)d_in[2];
    const float* b1    = (const float*)d_in[3];
    const float* W2    = (const float*)d_in[4];
    const float* b2    = (const float*)d_in[5];
    float* out = (float*)d_out;

    const int M = in_sizes[0] / HID;
    const int E = in_sizes[1] / 2;

    cudaFuncSetAttribute(node_proj_kernel,
                         cudaFuncAttributeMaxDynamicSharedMemorySize, (int)P1_SMEM);

    dim3 g1((M + 127) / 128, 2);
    node_proj_kernel<<<g1, 256, P1_SMEM>>>(hfeat, W1, b1, M);

    const int warps = (E + 7) / 8;                 // 8 edges per warp
    const int blocks = (warps + 7) / 8;            // 8 warps per CTA
    edge_kernel<<<blocks, 256>>>(eidx, W2, b2, out, E);
}

// round 6
// speedup vs baseline: 3.1136x; 1.0944x over previous
#include <cuda_runtime.h>
#include <cuda_fp16.h>
#include <cstdint>

// ---------------------------------------------------------------------------
// Edge-MLP link predictor, factorized + tensor-core phase 1:
//   P[n][0:128]   = h[n] @ W1[0:128,:]   + b1   (Pa, bias folded, fp16 store)
//   P[n][128:256] = h[n] @ W1[128:256,:]        (Pb, fp16 store)
//   out[e] = sigmoid( relu(Pa[src_e] + Pb[dst_e]) . W2 + b2 )
// Phase 1: mma.sync.m16n8k16, one CTA computes BOTH n-halves (h read once).
// Phase 2: half-warp per edge, 8 edges/warp, half2 relu-add, fp32 dot.
// ---------------------------------------------------------------------------

static constexpr int HID = 128;
static constexpr int MAXN = 50000;

__device__ __half g_P[(size_t)MAXN * 256];   // [node][0:128]=Pa, [128:256]=Pb

// ---------------- helpers ----------------

__device__ __forceinline__ uint32_t smem_u32(const void* p) {
    uint32_t a;
    asm("{ .reg .u64 t; cvta.to.shared.u64 t, %1; cvt.u32.u64 %0, t; }"
        : "=r"(a) : "l"(p));
    return a;
}

__device__ __forceinline__ uint32_t h2_bits(__half2 h) {
    return *reinterpret_cast<uint32_t*>(&h);
}

__device__ __forceinline__ void ldm_x4(uint32_t& a0, uint32_t& a1, uint32_t& a2,
                                       uint32_t& a3, uint32_t addr) {
    asm volatile("ldmatrix.sync.aligned.m8n8.x4.shared.b16 {%0,%1,%2,%3}, [%4];"
                 : "=r"(a0), "=r"(a1), "=r"(a2), "=r"(a3) : "r"(addr));
}

__device__ __forceinline__ void ldm_x2_t(uint32_t& b0, uint32_t& b1, uint32_t addr) {
    asm volatile("ldmatrix.sync.aligned.m8n8.x2.trans.shared.b16 {%0,%1}, [%2];"
                 : "=r"(b0), "=r"(b1) : "r"(addr));
}

__device__ __forceinline__ void mma16816(float& d0, float& d1, float& d2, float& d3,
                                         uint32_t a0, uint32_t a1, uint32_t a2,
                                         uint32_t a3, uint32_t b0, uint32_t b1) {
    asm volatile(
        "mma.sync.aligned.m16n8k16.row.col.f32.f16.f16.f32 "
        "{%0,%1,%2,%3}, {%4,%5,%6,%7}, {%8,%9}, {%0,%1,%2,%3};"
        : "+f"(d0), "+f"(d1), "+f"(d2), "+f"(d3)
        : "r"(a0), "r"(a1), "r"(a2), "r"(a3), "r"(b0), "r"(b1));
}

// ---------------- Phase 1: node projection GEMM (tensor cores) ----------------
// Grid ceil(M/128). CTA tile: 128 m x 128 n, K=128 full; loops half=0,1 over
// the two W1 row-blocks, reusing the As tile (h read/converted once).
// SMEM rows padded to 136 halfs (272B) -> ldmatrix conflict-free.
// 8 warps, warp tile 64m x 32n -> 4x4 grid of m16n8k16.

static constexpr int SROW = 136;                 // halfs per padded smem row
static constexpr uint32_t SROWB = SROW * 2;      // 272 bytes
static constexpr uint32_t P1_SMEM = 2u * 128u * SROWB;  // As + Bs

__global__ void __launch_bounds__(256, 1)
node_proj_kernel(const float* __restrict__ hfeat,
                 const float* __restrict__ W1,   // [256,128] row-major
                 const float* __restrict__ b1,   // [128]
                 int M) {
    extern __shared__ __align__(16) char smem[];
    char* As = smem;                         // [128][SROW] halfs, row = m
    char* Bs = smem + 128 * SROWB;           // [128][SROW] halfs, row = k
    const uint32_t as_b = smem_u32(As);
    const uint32_t bs_b = smem_u32(Bs);

    const int tid = threadIdx.x;
    const int m0  = blockIdx.x * 128;

    const int wid  = tid >> 5;
    const int lane = tid & 31;
    const int wm = (wid >> 2) * 64;          // warp m-origin (0 or 64)
    const int wn = (wid & 3) * 32;           // warp n-origin (0,32,64,96)
    const int l15 = lane & 15;
    const int khalf = (lane >> 4) * 8;
    const int r0 = lane >> 2;                // 0..7
    const int c0 = (lane & 3) * 2;           // 0,2,4,6

    // ---- load A once: h[m0+m][0:128] fp32 -> fp16 ----
    #pragma unroll
    for (int it = 0; it < 16; it++) {
        int i  = tid + it * 256;             // 4096 float4 groups
        int r  = i >> 5;
        int c4 = i & 31;
        int gm = m0 + r; if (gm >= M) gm = M - 1;
        float4 va = reinterpret_cast<const float4*>(hfeat)[(size_t)gm * 32 + c4];
        *reinterpret_cast<uint2*>(As + r * SROWB + c4 * 8) =
            make_uint2(h2_bits(__floats2half2_rn(va.x, va.y)),
                       h2_bits(__floats2half2_rn(va.z, va.w)));
    }

    #pragma unroll
    for (int half = 0; half < 2; half++) {
        // ---- load B: W1[half*128 + k][0:128] ----
        #pragma unroll
        for (int it = 0; it < 16; it++) {
            int i  = tid + it * 256;
            int r  = i >> 5;
            int c4 = i & 31;
            float4 vb = reinterpret_cast<const float4*>(W1)[(size_t)(half * 128 + r) * 32 + c4];
            *reinterpret_cast<uint2*>(Bs + r * SROWB + c4 * 8) =
                make_uint2(h2_bits(__floats2half2_rn(vb.x, vb.y)),
                           h2_bits(__floats2half2_rn(vb.z, vb.w)));
        }
        __syncthreads();

        float d[4][4][4];
        #pragma unroll
        for (int fm = 0; fm < 4; fm++)
            #pragma unroll
            for (int fn = 0; fn < 4; fn++)
                #pragma unroll
                for (int r = 0; r < 4; r++) d[fm][fn][r] = 0.0f;

        #pragma unroll
        for (int kk = 0; kk < 8; kk++) {
            const int k16 = kk * 16;
            uint32_t a[4][4];
            #pragma unroll
            for (int fm = 0; fm < 4; fm++) {
                uint32_t addr = as_b + (uint32_t)(wm + fm * 16 + l15) * SROWB +
                                (uint32_t)(k16 + khalf) * 2;
                ldm_x4(a[fm][0], a[fm][1], a[fm][2], a[fm][3], addr);
            }
            uint32_t b[4][2];
            #pragma unroll
            for (int fn = 0; fn < 4; fn++) {
                uint32_t addr = bs_b + (uint32_t)(k16 + l15) * SROWB +
                                (uint32_t)(wn + fn * 8) * 2;
                ldm_x2_t(b[fn][0], b[fn][1], addr);
            }
            #pragma unroll
            for (int fm = 0; fm < 4; fm++)
                #pragma unroll
                for (int fn = 0; fn < 4; fn++)
                    mma16816(d[fm][fn][0], d[fm][fn][1], d[fm][fn][2], d[fm][fn][3],
                             a[fm][0], a[fm][1], a[fm][2], a[fm][3],
                             b[fn][0], b[fn][1]);
        }

        // ---- epilogue: +b1 (half==0), fp16 pack, store to g_P ----
        #pragma unroll
        for (int fn = 0; fn < 4; fn++) {
            const int n = wn + fn * 8 + c0;      // even, 0..126
            float2 bias = make_float2(0.0f, 0.0f);
            if (half == 0) bias = *reinterpret_cast<const float2*>(b1 + n);
            #pragma unroll
            for (int fm = 0; fm < 4; fm++) {
                #pragma unroll
                for (int sub = 0; sub < 2; sub++) {
                    int gm = m0 + wm + fm * 16 + r0 + sub * 8;
                    if (gm < M) {
                        float x = d[fm][fn][sub * 2]     + bias.x;
                        float y = d[fm][fn][sub * 2 + 1] + bias.y;
                        *reinterpret_cast<__half2*>(g_P + (size_t)gm * 256 + half * 128 + n) =
                            __floats2half2_rn(x, y);
                    }
                }
            }
        }
        __syncthreads();   // Bs safe to overwrite for next half
    }
}

// ---------------- Phase 2: 8 edges per warp, half-warp per edge ----------------

__global__ void __launch_bounds__(256)
edge_kernel(const int* __restrict__ eidx,    // [2, E] int32
            const float* __restrict__ W2,    // [128]
            const float* __restrict__ b2,    // [1]
            float* __restrict__ out, int E) {
    const int warp = (blockIdx.x * blockDim.x + threadIdx.x) >> 5;
    const int lane = threadIdx.x & 31;
    const int hl  = lane >> 4;               // half-warp id (0/1)
    const int l16 = lane & 15;
    const int e0  = warp * 8;                // 8 edges per warp
    if (e0 >= E) return;

    // W2 slice for this lane: 8 floats (L1-resident broadcast)
    float4 w0 = reinterpret_cast<const float4*>(W2)[l16 * 2];
    float4 w1 = reinterpret_cast<const float4*>(W2)[l16 * 2 + 1];

    const char* Pbase = reinterpret_cast<const char*>(g_P);
    const uint32_t loff = (uint32_t)l16 << 4;   // lane byte offset within half-row

    // batch-load indices (4 iterations x 2 edges-per-warp via half-warps)
    int ev[4];
    uint32_t offa[4], offb[4];
    #pragma unroll
    for (int i = 0; i < 4; i++) {
        ev[i] = e0 + i * 2 + hl;
        bool ok = ev[i] < E;
        int sv = ok ? __ldg(eidx + ev[i]) : 0;
        int dv = ok ? __ldg(eidx + E + ev[i]) : 0;
        offa[i] = ((uint32_t)sv << 9) + loff;          // src row, Pa half
        offb[i] = ((uint32_t)dv << 9) + 256u + loff;   // dst row, Pb half
    }
    // batch-issue all 8 gathers (16B per lane each) for MLP
    uint4 va[4], vb[4];
    #pragma unroll
    for (int i = 0; i < 4; i++) {
        va[i] = *reinterpret_cast<const uint4*>(Pbase + offa[i]);
        vb[i] = *reinterpret_cast<const uint4*>(Pbase + offb[i]);
    }

    const float b2v = __ldg(b2);
    const __half2 z2 = __float2half2_rn(0.0f);
    const float wx[4] = {w0.x, w0.z, w1.x, w1.z};
    const float wy[4] = {w0.y, w0.w, w1.y, w1.w};

    #pragma unroll
    for (int i = 0; i < 4; i++) {
        const uint32_t* pa = &va[i].x;
        const uint32_t* pb = &vb[i].x;
        float acc = 0.0f;
        #pragma unroll
        for (int q = 0; q < 4; q++) {
            __half2 s = __hmax2(__hadd2(*reinterpret_cast<const __half2*>(&pa[q]),
                                        *reinterpret_cast<const __half2*>(&pb[q])), z2);
            float2 f = __half22float2(s);
            acc = fmaf(f.x, wx[q], acc);
            acc = fmaf(f.y, wy[q], acc);
        }
        #pragma unroll
        for (int off = 8; off > 0; off >>= 1)
            acc += __shfl_xor_sync(0xFFFFFFFFu, acc, off);
        if (l16 == 0 && ev[i] < E) {
            float x = acc + b2v;
            out[ev[i]] = 1.0f / (1.0f + expf(-x));
        }
    }
}

// ---------------- launch ----------------

extern "C" void kernel_launch(void* const* d_in, const int* in_sizes, int n_in,
                              void* d_out, int out_size) {
    const float* hfeat = (const float*)d_in[0];
    const int*   eidx  = (const int*)d_in[1];
    const float* W1    = (const float*)d_in[2];
    const float* b1    = (const float*)d_in[3];
    const float* W2    = (const float*)d_in[4];
    const float* b2    = (const float*)d_in[5];
    float* out = (float*)d_out;

    const int M = in_sizes[0] / HID;
    const int E = in_sizes[1] / 2;

    cudaFuncSetAttribute(node_proj_kernel,
                         cudaFuncAttributeMaxDynamicSharedMemorySize, (int)P1_SMEM);

    node_proj_kernel<<<(M + 127) / 128, 256, P1_SMEM>>>(hfeat, W1, b1, M);

    const int warps = (E + 7) / 8;                 // 8 edges per warp
    const int blocks = (warps + 7) / 8;            // 8 warps per CTA
    edge_kernel<<<blocks, 256>>>(eidx, W2, b2, out, E);
}

// round 7
// speedup vs baseline: 3.2962x; 1.0586x over previous
#include <cuda_runtime.h>
#include <cuda_fp16.h>
#include <cstdint>

// ---------------------------------------------------------------------------
// Edge-MLP link predictor, factorized + tensor-core phase 1:
//   P[n][0:128]   = h[n] @ W1[0:128,:]   + b1   (Pa, bias folded, fp16 store)
//   P[n][128:256] = h[n] @ W1[128:256,:]        (Pb, fp16 store)
//   out[e] = sigmoid( relu(Pa[src_e] + Pb[dst_e]) . W2 + b2 )
// Phase 1: persistent CTAs, W1 (both halves) SMEM-resident, 64-row A tiles.
// Phase 2: half-warp per edge, 8 edges/warp, fp16 hfma2 dot, fp32 finish.
// ---------------------------------------------------------------------------

static constexpr int HID = 128;
static constexpr int MAXN = 50000;

__device__ __half g_P[(size_t)MAXN * 256];   // [node][0:128]=Pa, [128:256]=Pb

// ---------------- helpers ----------------

__device__ __forceinline__ uint32_t smem_u32(const void* p) {
    uint32_t a;
    asm("{ .reg .u64 t; cvta.to.shared.u64 t, %1; cvt.u32.u64 %0, t; }"
        : "=r"(a) : "l"(p));
    return a;
}

__device__ __forceinline__ uint32_t h2_bits(__half2 h) {
    return *reinterpret_cast<uint32_t*>(&h);
}

__device__ __forceinline__ void ldm_x4(uint32_t& a0, uint32_t& a1, uint32_t& a2,
                                       uint32_t& a3, uint32_t addr) {
    asm volatile("ldmatrix.sync.aligned.m8n8.x4.shared.b16 {%0,%1,%2,%3}, [%4];"
                 : "=r"(a0), "=r"(a1), "=r"(a2), "=r"(a3) : "r"(addr));
}

__device__ __forceinline__ void ldm_x2_t(uint32_t& b0, uint32_t& b1, uint32_t addr) {
    asm volatile("ldmatrix.sync.aligned.m8n8.x2.trans.shared.b16 {%0,%1}, [%2];"
                 : "=r"(b0), "=r"(b1) : "r"(addr));
}

__device__ __forceinline__ void mma16816(float& d0, float& d1, float& d2, float& d3,
                                         uint32_t a0, uint32_t a1, uint32_t a2,
                                         uint32_t a3, uint32_t b0, uint32_t b1) {
    asm volatile(
        "mma.sync.aligned.m16n8k16.row.col.f32.f16.f16.f32 "
        "{%0,%1,%2,%3}, {%4,%5,%6,%7}, {%8,%9}, {%0,%1,%2,%3};"
        : "+f"(d0), "+f"(d1), "+f"(d2), "+f"(d3)
        : "r"(a0), "r"(a1), "r"(a2), "r"(a3), "r"(b0), "r"(b1));
}

// ---------------- Phase 1: persistent node projection GEMM ----------------
// 148 persistent CTAs. SMEM: As (64 rows) + Bs (256 rows = both W1 halves,
// loaded once). Rows padded to 136 halfs (272B) for ldmatrix.
// Per 64-row tile: batched LDG of h -> fp16 As, then per half: 8 k-steps of
// m16n8k16 over warp tile 32m x 32n, epilogue +b1/store fp16 to g_P.

static constexpr int SROW = 136;                 // halfs per padded smem row
static constexpr uint32_t SROWB = SROW * 2;      // 272 bytes
static constexpr uint32_t AS_BYTES = 64u * SROWB;        // 17408
static constexpr uint32_t BS_BYTES = 256u * SROWB;       // 69632
static constexpr uint32_t P1_SMEM  = AS_BYTES + BS_BYTES;

__global__ void __launch_bounds__(256, 1)
node_proj_kernel(const float* __restrict__ hfeat,
                 const float* __restrict__ W1,   // [256,128] row-major
                 const float* __restrict__ b1,   // [128]
                 int M, int n_tiles) {
    extern __shared__ __align__(16) char smem[];
    char* As = smem;                          // [64][SROW] halfs, row = m
    char* Bs = smem + AS_BYTES;               // [256][SROW] halfs, row = k (half*128+k)
    const uint32_t as_b = smem_u32(As);
    const uint32_t bs_b = smem_u32(Bs);

    const int tid = threadIdx.x;
    const int wid  = tid >> 5;
    const int lane = tid & 31;
    const int wm = (wid >> 2) * 32;           // warp m-origin (0 or 32)
    const int wn = (wid & 3) * 32;            // warp n-origin
    const int l15 = lane & 15;
    const int khalf = (lane >> 4) * 8;
    const int r0 = lane >> 2;
    const int c0 = (lane & 3) * 2;

    // ---- load W1 (both halves) once: 256 rows x 128 cols fp32 -> fp16 ----
    #pragma unroll
    for (int it = 0; it < 32; it++) {
        int i  = tid + it * 256;              // 8192 float4 groups
        int r  = i >> 5;                      // 0..255
        int c4 = i & 31;
        float4 vb = reinterpret_cast<const float4*>(W1)[(size_t)r * 32 + c4];
        *reinterpret_cast<uint2*>(Bs + r * SROWB + c4 * 8) =
            make_uint2(h2_bits(__floats2half2_rn(vb.x, vb.y)),
                       h2_bits(__floats2half2_rn(vb.z, vb.w)));
    }

    // A-load mapping: thread handles 8 float4 = rows (tid>>5)+8*it? Use
    // i = tid + it*256 -> r = i>>5 (0..63), c4 = i&31.
    for (int tile = blockIdx.x; tile < n_tiles; tile += gridDim.x) {
        const int m0 = tile * 64;

        // batched global loads first (MLP), then convert+STS
        float4 va[8];
        #pragma unroll
        for (int it = 0; it < 8; it++) {
            int i  = tid + it * 256;
            int r  = i >> 5;
            int c4 = i & 31;
            int gm = m0 + r; if (gm >= M) gm = M - 1;
            va[it] = reinterpret_cast<const float4*>(hfeat)[(size_t)gm * 32 + c4];
        }
        __syncthreads();   // previous tile's MMA reads of As complete
        #pragma unroll
        for (int it = 0; it < 8; it++) {
            int i  = tid + it * 256;
            int r  = i >> 5;
            int c4 = i & 31;
            *reinterpret_cast<uint2*>(As + r * SROWB + c4 * 8) =
                make_uint2(h2_bits(__floats2half2_rn(va[it].x, va[it].y)),
                           h2_bits(__floats2half2_rn(va[it].z, va[it].w)));
        }
        __syncthreads();

        #pragma unroll
        for (int half = 0; half < 2; half++) {
            float d[2][4][4];
            #pragma unroll
            for (int fm = 0; fm < 2; fm++)
                #pragma unroll
                for (int fn = 0; fn < 4; fn++)
                    #pragma unroll
                    for (int r = 0; r < 4; r++) d[fm][fn][r] = 0.0f;

            const uint32_t bs_h = bs_b + (uint32_t)(half * 128) * SROWB;

            #pragma unroll
            for (int kk = 0; kk < 8; kk++) {
                const int k16 = kk * 16;
                uint32_t a[2][4];
                #pragma unroll
                for (int fm = 0; fm < 2; fm++) {
                    uint32_t addr = as_b + (uint32_t)(wm + fm * 16 + l15) * SROWB +
                                    (uint32_t)(k16 + khalf) * 2;
                    ldm_x4(a[fm][0], a[fm][1], a[fm][2], a[fm][3], addr);
                }
                uint32_t b[4][2];
                #pragma unroll
                for (int fn = 0; fn < 4; fn++) {
                    uint32_t addr = bs_h + (uint32_t)(k16 + l15) * SROWB +
                                    (uint32_t)(wn + fn * 8) * 2;
                    ldm_x2_t(b[fn][0], b[fn][1], addr);
                }
                #pragma unroll
                for (int fm = 0; fm < 2; fm++)
                    #pragma unroll
                    for (int fn = 0; fn < 4; fn++)
                        mma16816(d[fm][fn][0], d[fm][fn][1], d[fm][fn][2], d[fm][fn][3],
                                 a[fm][0], a[fm][1], a[fm][2], a[fm][3],
                                 b[fn][0], b[fn][1]);
            }

            // epilogue: +b1 (half==0), fp16 pack, store
            #pragma unroll
            for (int fn = 0; fn < 4; fn++) {
                const int n = wn + fn * 8 + c0;
                float2 bias = make_float2(0.0f, 0.0f);
                if (half == 0) bias = *reinterpret_cast<const float2*>(b1 + n);
                #pragma unroll
                for (int fm = 0; fm < 2; fm++) {
                    #pragma unroll
                    for (int sub = 0; sub < 2; sub++) {
                        int gm = m0 + wm + fm * 16 + r0 + sub * 8;
                        if (gm < M) {
                            float x = d[fm][fn][sub * 2]     + bias.x;
                            float y = d[fm][fn][sub * 2 + 1] + bias.y;
                            *reinterpret_cast<__half2*>(
                                g_P + (size_t)gm * 256 + half * 128 + n) =
                                __floats2half2_rn(x, y);
                        }
                    }
                }
            }
        }
    }
}

// ---------------- Phase 2: 8 edges per warp, half-warp per edge ----------------

__global__ void __launch_bounds__(256)
edge_kernel(const int* __restrict__ eidx,    // [2, E] int32
            const float* __restrict__ W2,    // [128]
            const float* __restrict__ b2,    // [1]
            float* __restrict__ out, int E) {
    const int warp = (blockIdx.x * blockDim.x + threadIdx.x) >> 5;
    const int lane = threadIdx.x & 31;
    const int hl  = lane >> 4;               // half-warp id (0/1)
    const int l16 = lane & 15;
    const int e0  = warp * 8;                // 8 edges per warp
    if (e0 >= E) return;

    // W2 slice -> fp16 half2 x4 per lane
    float4 w0 = reinterpret_cast<const float4*>(W2)[l16 * 2];
    float4 w1 = reinterpret_cast<const float4*>(W2)[l16 * 2 + 1];
    __half2 w2h[4];
    w2h[0] = __floats2half2_rn(w0.x, w0.y);
    w2h[1] = __floats2half2_rn(w0.z, w0.w);
    w2h[2] = __floats2half2_rn(w1.x, w1.y);
    w2h[3] = __floats2half2_rn(w1.z, w1.w);

    const char* Pbase = reinterpret_cast<const char*>(g_P);
    const uint32_t loff = (uint32_t)l16 << 4;   // lane byte offset within half-row

    int ev[4];
    uint32_t offa[4], offb[4];
    #pragma unroll
    for (int i = 0; i < 4; i++) {
        ev[i] = e0 + i * 2 + hl;
        bool ok = ev[i] < E;
        int sv = ok ? __ldg(eidx + ev[i]) : 0;
        int dv = ok ? __ldg(eidx + E + ev[i]) : 0;
        offa[i] = ((uint32_t)sv << 9) + loff;          // src row, Pa half
        offb[i] = ((uint32_t)dv << 9) + 256u + loff;   // dst row, Pb half
    }
    uint4 va[4], vb[4];
    #pragma unroll
    for (int i = 0; i < 4; i++) {
        va[i] = *reinterpret_cast<const uint4*>(Pbase + offa[i]);
        vb[i] = *reinterpret_cast<const uint4*>(Pbase + offb[i]);
    }

    const float b2v = __ldg(b2);
    const __half2 z2 = __float2half2_rn(0.0f);

    #pragma unroll
    for (int i = 0; i < 4; i++) {
        const uint32_t* pa = &va[i].x;
        const uint32_t* pb = &vb[i].x;
        __half2 t = __hmul2(__hmax2(__hadd2(*reinterpret_cast<const __half2*>(&pa[0]),
                                            *reinterpret_cast<const __half2*>(&pb[0])), z2),
                            w2h[0]);
        #pragma unroll
        for (int q = 1; q < 4; q++)
            t = __hfma2(__hmax2(__hadd2(*reinterpret_cast<const __half2*>(&pa[q]),
                                        *reinterpret_cast<const __half2*>(&pb[q])), z2),
                        w2h[q], t);
        float2 f = __half22float2(t);
        float acc = f.x + f.y;
        #pragma unroll
        for (int off = 8; off > 0; off >>= 1)
            acc += __shfl_xor_sync(0xFFFFFFFFu, acc, off);
        if (l16 == 0 && ev[i] < E) {
            float x = acc + b2v;
            out[ev[i]] = 1.0f / (1.0f + __expf(-x));
        }
    }
}

// ---------------- launch ----------------

extern "C" void kernel_launch(void* const* d_in, const int* in_sizes, int n_in,
                              void* d_out, int out_size) {
    const float* hfeat = (const float*)d_in[0];
    const int*   eidx  = (const int*)d_in[1];
    const float* W1    = (const float*)d_in[2];
    const float* b1    = (const float*)d_in[3];
    const float* W2    = (const float*)d_in[4];
    const float* b2    = (const float*)d_in[5];
    float* out = (float*)d_out;

    const int M = in_sizes[0] / HID;
    const int E = in_sizes[1] / 2;
    const int n_tiles = (M + 63) / 64;

    cudaFuncSetAttribute(node_proj_kernel,
                         cudaFuncAttributeMaxDynamicSharedMemorySize, (int)P1_SMEM);

    int grid1 = 148;
    if (grid1 > n_tiles) grid1 = n_tiles;
    node_proj_kernel<<<grid1, 256, P1_SMEM>>>(hfeat, W1, b1, M, n_tiles);

    const int warps = (E + 7) / 8;                 // 8 edges per warp
    const int blocks = (warps + 7) / 8;            // 8 warps per CTA
    edge_kernel<<<blocks, 256>>>(eidx, W2, b2, out, E);
}

// round 8
// speedup vs baseline: 3.4021x; 1.0321x over previous
#include <cuda_runtime.h>
#include <cuda_fp16.h>
#include <cstdint>

// ---------------------------------------------------------------------------
// Edge-MLP link predictor, factorized + tensor-core phase 1:
//   P[n][0:128]   = h[n] @ W1[0:128,:]   + b1   (Pa, bias folded, fp16 store)
//   P[n][128:256] = h[n] @ W1[128:256,:]        (Pb, fp16 store)
//   out[e] = sigmoid( relu(Pa[src_e] + Pb[dst_e]) . W2 + b2 )
// Phase 1: persistent CTAs, W1 SMEM-resident, software-pipelined A tiles
//          (LDG of tile t+1 issued before MMA of tile t), x4.trans B LDSM.
// Phase 2: half-warp per edge, 4 edges/warp (low regs, high occ), fp16 dot.
// ---------------------------------------------------------------------------

static constexpr int HID = 128;
static constexpr int MAXN = 50000;

__device__ __half g_P[(size_t)MAXN * 256];   // [node][0:128]=Pa, [128:256]=Pb

// ---------------- helpers ----------------

__device__ __forceinline__ uint32_t smem_u32(const void* p) {
    uint32_t a;
    asm("{ .reg .u64 t; cvta.to.shared.u64 t, %1; cvt.u32.u64 %0, t; }"
        : "=r"(a) : "l"(p));
    return a;
}

__device__ __forceinline__ uint32_t h2_bits(__half2 h) {
    return *reinterpret_cast<uint32_t*>(&h);
}

__device__ __forceinline__ void ldm_x4(uint32_t& a0, uint32_t& a1, uint32_t& a2,
                                       uint32_t& a3, uint32_t addr) {
    asm volatile("ldmatrix.sync.aligned.m8n8.x4.shared.b16 {%0,%1,%2,%3}, [%4];"
                 : "=r"(a0), "=r"(a1), "=r"(a2), "=r"(a3) : "r"(addr));
}

__device__ __forceinline__ void ldm_x4_t(uint32_t& b0, uint32_t& b1, uint32_t& b2,
                                         uint32_t& b3, uint32_t addr) {
    asm volatile("ldmatrix.sync.aligned.m8n8.x4.trans.shared.b16 {%0,%1,%2,%3}, [%4];"
                 : "=r"(b0), "=r"(b1), "=r"(b2), "=r"(b3) : "r"(addr));
}

__device__ __forceinline__ void mma16816(float& d0, float& d1, float& d2, float& d3,
                                         uint32_t a0, uint32_t a1, uint32_t a2,
                                         uint32_t a3, uint32_t b0, uint32_t b1) {
    asm volatile(
        "mma.sync.aligned.m16n8k16.row.col.f32.f16.f16.f32 "
        "{%0,%1,%2,%3}, {%4,%5,%6,%7}, {%8,%9}, {%0,%1,%2,%3};"
        : "+f"(d0), "+f"(d1), "+f"(d2), "+f"(d3)
        : "r"(a0), "r"(a1), "r"(a2), "r"(a3), "r"(b0), "r"(b1));
}

// ---------------- Phase 1: persistent node projection GEMM ----------------

static constexpr int SROW = 136;                 // halfs per padded smem row
static constexpr uint32_t SROWB = SROW * 2;      // 272 bytes
static constexpr uint32_t AS_BYTES = 64u * SROWB;
static constexpr uint32_t BS_BYTES = 256u * SROWB;
static constexpr uint32_t P1_SMEM  = AS_BYTES + BS_BYTES;

__global__ void __launch_bounds__(256, 1)
node_proj_kernel(const float* __restrict__ hfeat,
                 const float* __restrict__ W1,   // [256,128] row-major
                 const float* __restrict__ b1,   // [128]
                 int M, int n_tiles) {
    extern __shared__ __align__(16) char smem[];
    char* As = smem;                          // [64][SROW] halfs, row = m
    char* Bs = smem + AS_BYTES;               // [256][SROW] halfs, row = half*128+k
    const uint32_t as_b = smem_u32(As);
    const uint32_t bs_b = smem_u32(Bs);

    const int tid = threadIdx.x;
    const int wid  = tid >> 5;
    const int lane = tid & 31;
    const int wm = (wid >> 2) * 32;           // warp m-origin (0 or 32)
    const int wn = (wid & 3) * 32;            // warp n-origin
    const int l15 = lane & 15;
    const int khalf = (lane >> 4) * 8;
    const int r0 = lane >> 2;
    const int c0 = (lane & 3) * 2;
    // B x4.trans lane addressing: rows k16 + (g&1)*8 + (lane&7), col block (g>>1)
    const int brow = ((lane >> 3) & 1) * 8 + (lane & 7);
    const int bcol = (lane >> 4) * 8;

    // ---- load W1 (both halves) once ----
    #pragma unroll
    for (int it = 0; it < 32; it++) {
        int i  = tid + it * 256;
        int r  = i >> 5;
        int c4 = i & 31;
        float4 vb = reinterpret_cast<const float4*>(W1)[(size_t)r * 32 + c4];
        *reinterpret_cast<uint2*>(Bs + r * SROWB + c4 * 8) =
            make_uint2(h2_bits(__floats2half2_rn(vb.x, vb.y)),
                       h2_bits(__floats2half2_rn(vb.z, vb.w)));
    }

    // per-thread A-load mapping (same every tile)
    const int ar  = tid >> 5;                 // base row (0..7 step handled by it)
    const int ac4 = tid & 31;

    int tile = blockIdx.x;
    float4 va[8];
    if (tile < n_tiles) {
        const int m0 = tile * 64;
        #pragma unroll
        for (int it = 0; it < 8; it++) {
            int r = ar + it * 8;
            int gm = m0 + r; if (gm >= M) gm = M - 1;
            va[it] = reinterpret_cast<const float4*>(hfeat)[(size_t)gm * 32 + ac4];
        }
    }

    while (tile < n_tiles) {
        const int m0 = tile * 64;
        const int next = tile + gridDim.x;

        __syncthreads();   // previous tile's MMA reads of As complete
        #pragma unroll
        for (int it = 0; it < 8; it++) {
            int r = ar + it * 8;
            *reinterpret_cast<uint2*>(As + r * SROWB + ac4 * 8) =
                make_uint2(h2_bits(__floats2half2_rn(va[it].x, va[it].y)),
                           h2_bits(__floats2half2_rn(va[it].z, va[it].w)));
        }
        __syncthreads();

        // prefetch next tile's A while MMA runs
        if (next < n_tiles) {
            const int m1 = next * 64;
            #pragma unroll
            for (int it = 0; it < 8; it++) {
                int r = ar + it * 8;
                int gm = m1 + r; if (gm >= M) gm = M - 1;
                va[it] = reinterpret_cast<const float4*>(hfeat)[(size_t)gm * 32 + ac4];
            }
        }

        #pragma unroll
        for (int half = 0; half < 2; half++) {
            float d[2][4][4];
            #pragma unroll
            for (int fm = 0; fm < 2; fm++)
                #pragma unroll
                for (int fn = 0; fn < 4; fn++)
                    #pragma unroll
                    for (int r = 0; r < 4; r++) d[fm][fn][r] = 0.0f;

            const uint32_t bs_h = bs_b + (uint32_t)(half * 128) * SROWB;

            #pragma unroll
            for (int kk = 0; kk < 8; kk++) {
                const int k16 = kk * 16;
                uint32_t a[2][4];
                #pragma unroll
                for (int fm = 0; fm < 2; fm++) {
                    uint32_t addr = as_b + (uint32_t)(wm + fm * 16 + l15) * SROWB +
                                    (uint32_t)(k16 + khalf) * 2;
                    ldm_x4(a[fm][0], a[fm][1], a[fm][2], a[fm][3], addr);
                }
                uint32_t b[4][2];
                #pragma unroll
                for (int fnp = 0; fnp < 2; fnp++) {
                    uint32_t addr = bs_h + (uint32_t)(k16 + brow) * SROWB +
                                    (uint32_t)(wn + fnp * 16 + bcol) * 2;
                    ldm_x4_t(b[2 * fnp][0], b[2 * fnp][1],
                             b[2 * fnp + 1][0], b[2 * fnp + 1][1], addr);
                }
                #pragma unroll
                for (int fm = 0; fm < 2; fm++)
                    #pragma unroll
                    for (int fn = 0; fn < 4; fn++)
                        mma16816(d[fm][fn][0], d[fm][fn][1], d[fm][fn][2], d[fm][fn][3],
                                 a[fm][0], a[fm][1], a[fm][2], a[fm][3],
                                 b[fn][0], b[fn][1]);
            }

            // epilogue: +b1 (half==0), fp16 pack, store
            #pragma unroll
            for (int fn = 0; fn < 4; fn++) {
                const int n = wn + fn * 8 + c0;
                float2 bias = make_float2(0.0f, 0.0f);
                if (half == 0) bias = *reinterpret_cast<const float2*>(b1 + n);
                #pragma unroll
                for (int fm = 0; fm < 2; fm++) {
                    #pragma unroll
                    for (int sub = 0; sub < 2; sub++) {
                        int gm = m0 + wm + fm * 16 + r0 + sub * 8;
                        if (gm < M) {
                            float x = d[fm][fn][sub * 2]     + bias.x;
                            float y = d[fm][fn][sub * 2 + 1] + bias.y;
                            *reinterpret_cast<__half2*>(
                                g_P + (size_t)gm * 256 + half * 128 + n) =
                                __floats2half2_rn(x, y);
                        }
                    }
                }
            }
        }
        tile = next;
    }
}

// ---------------- Phase 2: 4 edges per warp, half-warp per edge ----------------

__global__ void __launch_bounds__(256)
edge_kernel(const int* __restrict__ eidx,    // [2, E] int32
            const float* __restrict__ W2,    // [128]
            const float* __restrict__ b2,    // [1]
            float* __restrict__ out, int E) {
    const int warp = (blockIdx.x * blockDim.x + threadIdx.x) >> 5;
    const int lane = threadIdx.x & 31;
    const int hl  = lane >> 4;
    const int l16 = lane & 15;
    const int e0  = warp * 4;                // 4 edges per warp
    if (e0 >= E) return;

    // W2 slice -> fp16 half2 x4 per lane
    float4 w0 = reinterpret_cast<const float4*>(W2)[l16 * 2];
    float4 w1 = reinterpret_cast<const float4*>(W2)[l16 * 2 + 1];
    __half2 w2h[4];
    w2h[0] = __floats2half2_rn(w0.x, w0.y);
    w2h[1] = __floats2half2_rn(w0.z, w0.w);
    w2h[2] = __floats2half2_rn(w1.x, w1.y);
    w2h[3] = __floats2half2_rn(w1.z, w1.w);

    const char* Pbase = reinterpret_cast<const char*>(g_P);
    const uint32_t loff = (uint32_t)l16 << 4;

    int ev[2];
    uint32_t offa[2], offb[2];
    #pragma unroll
    for (int i = 0; i < 2; i++) {
        ev[i] = e0 + i * 2 + hl;
        bool ok = ev[i] < E;
        int sv = ok ? __ldg(eidx + ev[i]) : 0;
        int dv = ok ? __ldg(eidx + E + ev[i]) : 0;
        offa[i] = ((uint32_t)sv << 9) + loff;
        offb[i] = ((uint32_t)dv << 9) + 256u + loff;
    }
    uint4 va[2], vb[2];
    #pragma unroll
    for (int i = 0; i < 2; i++) {
        va[i] = *reinterpret_cast<const uint4*>(Pbase + offa[i]);
        vb[i] = *reinterpret_cast<const uint4*>(Pbase + offb[i]);
    }

    const float b2v = __ldg(b2);
    const __half2 z2 = __float2half2_rn(0.0f);

    #pragma unroll
    for (int i = 0; i < 2; i++) {
        const uint32_t* pa = &va[i].x;
        const uint32_t* pb = &vb[i].x;
        __half2 t = __hmul2(__hmax2(__hadd2(*reinterpret_cast<const __half2*>(&pa[0]),
                                            *reinterpret_cast<const __half2*>(&pb[0])), z2),
                            w2h[0]);
        #pragma unroll
        for (int q = 1; q < 4; q++)
            t = __hfma2(__hmax2(__hadd2(*reinterpret_cast<const __half2*>(&pa[q]),
                                        *reinterpret_cast<const __half2*>(&pb[q])), z2),
                        w2h[q], t);
        float2 f = __half22float2(t);
        float acc = f.x + f.y;
        #pragma unroll
        for (int off = 8; off > 0; off >>= 1)
            acc += __shfl_xor_sync(0xFFFFFFFFu, acc, off);
        if (l16 == 0 && ev[i] < E) {
            float x = acc + b2v;
            out[ev[i]] = 1.0f / (1.0f + __expf(-x));
        }
    }
}

// ---------------- launch ----------------

extern "C" void kernel_launch(void* const* d_in, const int* in_sizes, int n_in,
                              void* d_out, int out_size) {
    const float* hfeat = (const float*)d_in[0];
    const int*   eidx  = (const int*)d_in[1];
    const float* W1    = (const float*)d_in[2];
    const float* b1    = (const float*)d_in[3];
    const float* W2    = (const float*)d_in[4];
    const float* b2    = (const float*)d_in[5];
    float* out = (float*)d_out;

    const int M = in_sizes[0] / HID;
    const int E = in_sizes[1] / 2;
    const int n_tiles = (M + 63) / 64;

    cudaFuncSetAttribute(node_proj_kernel,
                         cudaFuncAttributeMaxDynamicSharedMemorySize, (int)P1_SMEM);

    int grid1 = 148;
    if (grid1 > n_tiles) grid1 = n_tiles;
    node_proj_kernel<<<grid1, 256, P1_SMEM>>>(hfeat, W1, b1, M, n_tiles);

    const int warps = (E + 3) / 4;                 // 4 edges per warp
    const int blocks = (warps + 7) / 8;            // 8 warps per CTA
    edge_kernel<<<blocks, 256>>>(eidx, W2, b2, out, E);
}